// round 13
// baseline (speedup 1.0000x reference)
#include <cuda_runtime.h>
#include <stdint.h>

#define D 256
#define BQ 1024
#define KTOP 1024
#define MMAX 100000
#define CAND_MAX 4096
#define FEAT_BLOCKS 128
#define HBITS 13
#define HBINS (1 << HBITS)     // 8192 bins
#define GRID 592               // 4 per SM * 148 — regfile-exact co-residency
#define TB 256
#define NBAR 5

typedef unsigned long long ull;

// ---------------- static device scratch ----------------
__device__ ull g_bar;                  // monotonic grid-barrier counter
__device__ float g_pfsum[FEAT_BLOCKS][D];
__device__ ull g_keys[MMAX];
__device__ int g_hist[HBINS];          // 32 KB
__device__ int g_Tbin;
__device__ ull g_cand[CAND_MAX];
__device__ int g_ncand;
__device__ int g_topidx[KTOP];

// ---------------- grid barrier (replay-safe, monotonic epoch base) ----------------
__device__ __forceinline__ void gbar(int k, ull* sbase) {
    __threadfence();                 // release (gpu scope)
    __syncthreads();
    if (threadIdx.x == 0) {
        ull old = atomicAdd(&g_bar, 1ULL);
        if (k == 0) *sbase = old - (old % (ull)(GRID * NBAR));
        ull target = *sbase + (ull)(k + 1) * GRID;
        while (*(volatile ull*)&g_bar < target) __nanosleep(32);
    }
    __syncthreads();
    __threadfence();                 // acquire + L1D invalidate
}

// packed f32x2 FMA (sm_103a FFMA2 — PTX-only)
__device__ __forceinline__ ull fma2(ull a, ull b, ull c) {
    ull d;
    asm("fma.rn.f32x2 %0, %1, %2, %3;" : "=l"(d) : "l"(a), "l"(b), "l"(c));
    return d;
}
__device__ __forceinline__ float unpack_add(ull v) {
    float lo, hi;
    asm("mov.b64 {%0, %1}, %2;" : "=f"(lo), "=f"(hi) : "l"(v));
    return lo + hi;
}

// inclusive suffix-sum over 256 values (one per thread, 8 warps)
__device__ __forceinline__ int suffix256(int v, int t, int lane, int w, int* wsum) {
#pragma unroll
    for (int off = 1; off < 32; off <<= 1) {
        int u = __shfl_down_sync(0xffffffffu, v, off);
        if (lane + off < 32) v += u;
    }
    if (lane == 0) wsum[w] = v;
    __syncthreads();
    if (t < 8) {
        int wv = wsum[t];
#pragma unroll
        for (int off = 1; off < 8; off <<= 1) {
            int u = __shfl_down_sync(0x000000ffu, wv, off);
            if (t + off < 8) wv += u;
        }
        wsum[t] = wv;
    }
    __syncthreads();
    return v + ((w < 7) ? wsum[w + 1] : 0);
}

// load 4 rows (2 ulonglong2 = 4 packed pairs per row per lane), clamped
__device__ __forceinline__ void load4(const float* __restrict__ mem, int rb, int M,
                                      int lane, ulonglong2* A) {
#pragma unroll
    for (int r = 0; r < 4; r++) {
        int row = rb + r;
        if (row >= M) row = M - 1;
        const ulonglong2* m2 = (const ulonglong2*)(mem + (size_t)row * D);
        A[r * 2]     = m2[lane * 2];
        A[r * 2 + 1] = m2[lane * 2 + 1];
    }
}

// ---------------- the mega kernel ----------------
__global__ void __launch_bounds__(TB, 4)
k_mega(const float* __restrict__ feat, const float* __restrict__ mem,
       float* __restrict__ out, int M) {
    __shared__ __align__(16) char s_buf[CAND_MAX * 8];  // 32 KB: shist (P2) / sk (P5)
    __shared__ __align__(16) float sf[D];               // 1 KB: -2*fsum
    __shared__ ull sbase;
    __shared__ int s_ssuf[TB];
    __shared__ int s_wsum[8];

    int t = threadIdx.x, blk = blockIdx.x;
    int warp = t >> 5, lane = t & 31;

    // ---- P0: zero hist + ncand; feature partial sums (blocks 0..127) ----
    {
        int i = blk * TB + t;
        if (i < HBINS) g_hist[i] = 0;
        if (i == 0) g_ncand = 0;
        if (blk < FEAT_BLOCKS) {
            const int RPB = BQ / FEAT_BLOCKS;  // 8
            float s = 0.f;
            int base = blk * RPB * D + t;
#pragma unroll
            for (int r = 0; r < RPB; r++) s += feat[base + r * D];
            g_pfsum[blk][t] = s;
        }
    }
    gbar(0, &sbase);

    // ---- P1 (fused): every block redundantly reduces partials — EXACT serial
    // order per dim as R4..R12 -> bit-identical sf in all blocks, no barrier ----
    {
        float s = 0.f;
#pragma unroll 16
        for (int b = 0; b < FEAT_BLOCKS; b++) s += g_pfsum[b][t];
        sf[t] = -2.f * s;
    }

    // ---- P2: scores — pipelined loads, packed FMA, 6-shfl reduction ----
    {
        int* shist = (int*)s_buf;
#pragma unroll
        for (int i = t; i < HBINS; i += TB) shist[i] = 0;
        __syncthreads();

        const ulonglong2* f2p = (const ulonglong2*)sf;
        ulonglong2 fA = f2p[lane * 2], fB = f2p[lane * 2 + 1];
        const ull B2 = 0x4480000044800000ULL;  // (1024.f, 1024.f)

        const int STRIDE = GRID * 8 * 4;       // 18944
        int gw = blk * 8 + warp;
        int rb = gw * 4;
        // winner-lane mapping: lanes {0,16,8,24} -> rows +{0,1,2,3}
        int wrow = (lane == 0) ? 0 : (lane == 16) ? 1 : (lane == 8) ? 2
                 : (lane == 24) ? 3 : -1;
        if (rb < M) {
            ulonglong2 A[8];                   // current 4 rows
            load4(mem, rb, M, lane, A);
            while (rb < M) {
                int rb2 = rb + STRIDE;
                ulonglong2 C[8];               // prefetch next 4 rows
                if (rb2 < M) load4(mem, rb2, M, lane, C);

                float acc[4];
#pragma unroll
                for (int r = 0; r < 4; r++) {
                    ull a0 = A[r * 2].x, a1 = A[r * 2].y;
                    ull b0 = A[r * 2 + 1].x, b1 = A[r * 2 + 1].y;
                    ull s2 = fma2(a0, fma2(B2, a0, fA.x), 0ULL);
                    s2 = fma2(a1, fma2(B2, a1, fA.y), s2);
                    s2 = fma2(b0, fma2(B2, b0, fB.x), s2);
                    s2 = fma2(b1, fma2(B2, b1, fB.y), s2);
                    acc[r] = unpack_add(s2);
                }
                // merged reduction: pairing identical to xor-16/8/4/2/1 butterfly
                bool hi16 = (lane & 16) != 0;
                float q0 = __shfl_xor_sync(0xffffffffu, hi16 ? acc[0] : acc[1], 16);
                float z  = (hi16 ? acc[1] : acc[0]) + q0;
                float q1 = __shfl_xor_sync(0xffffffffu, hi16 ? acc[2] : acc[3], 16);
                float w2 = (hi16 ? acc[3] : acc[2]) + q1;
                bool hi8 = (lane & 8) != 0;
                float q2 = __shfl_xor_sync(0xffffffffu, hi8 ? z : w2, 8);
                float v  = (hi8 ? w2 : z) + q2;
                v += __shfl_xor_sync(0xffffffffu, v, 4);
                v += __shfl_xor_sync(0xffffffffu, v, 2);
                v += __shfl_xor_sync(0xffffffffu, v, 1);

                if (wrow >= 0 && rb + wrow < M) {
                    int row = rb + wrow;
                    float score = -v;
                    unsigned u = __float_as_uint(score);
                    u = (u & 0x80000000u) ? ~u : (u | 0x80000000u);
                    g_keys[row] = ((ull)u << 32) | (unsigned)(~row);
                    atomicAdd(&shist[u >> (32 - HBITS)], 1);
                }
#pragma unroll
                for (int j = 0; j < 8; j++) A[j] = C[j];
                rb = rb2;
            }
        }
        __syncthreads();    // all block atomics into shist done
        for (int i = t; i < HBINS; i += TB) {
            int v = shist[i];
            if (v) atomicAdd(&g_hist[i], v);
        }
    }
    gbar(1, &sbase);

    // ---- P3: threshold — single pass, in-register refine (block 0) ----
    if (blk == 0) {
        int h[32];                      // bins [t*32, t*32+32)
        const int4* p4 = (const int4*)(g_hist + t * 32);
        int s = 0;
#pragma unroll
        for (int j = 0; j < 8; j++) {
            int4 v = p4[j];
            h[j * 4] = v.x; h[j * 4 + 1] = v.y; h[j * 4 + 2] = v.z; h[j * 4 + 3] = v.w;
            s += v.x + v.y + v.z + v.w;
        }
        int suf = suffix256(s, t, lane, warp, s_wsum);
        s_ssuf[t] = suf;
        __syncthreads();
        if (suf >= KTOP && (t == TB - 1 || s_ssuf[t + 1] < KTOP)) {
            int cum = (t == TB - 1) ? 0 : s_ssuf[t + 1];
#pragma unroll
            for (int j = 31; j >= 0; j--) {
                cum += h[j];
                if (cum >= KTOP) { g_Tbin = t * 32 + j; break; }
            }
        }
    }
    gbar(2, &sbase);

    // ---- P4: collect candidates ----
    {
        int Tb = g_Tbin;
        for (int i = blk * TB + t; i < M; i += GRID * TB) {
            ull key = g_keys[i];
            if ((int)(key >> (64 - HBITS)) >= Tb) {
                int p = atomicAdd(&g_ncand, 1);
                if (p < CAND_MAX) g_cand[p] = key;
            }
        }
    }
    gbar(3, &sbase);

    // ---- P5: exact rank — warp per candidate (keys unique) ----
    {
        ull* sk = (ull*)s_buf;
        int n = g_ncand;
        if (n > CAND_MAX) n = CAND_MAX;
        for (int j = t; j < n; j += TB) sk[j] = g_cand[j];
        __syncthreads();
        for (int c = blk * 8 + warp; c < n; c += GRID * 8) {
            ull me = sk[c];
            int cnt = 0;
            for (int j = lane; j < n; j += 32) cnt += (sk[j] > me);
#pragma unroll
            for (int o = 16; o > 0; o >>= 1)
                cnt += __shfl_down_sync(0xffffffffu, cnt, o);
            if (lane == 0 && cnt < KTOP) g_topidx[cnt] = (int)(~(unsigned)me);
        }
    }
    gbar(4, &sbase);

    // ---- P6: gather winning rows ----
    for (int rr = blk * 4 + (t >> 6); rr < KTOP; rr += GRID * 4) {
        int idx = g_topidx[rr];
        const float4* src = (const float4*)(mem + (size_t)idx * D);
        float4* dst = (float4*)(out + (size_t)rr * D);
        dst[t & 63] = src[t & 63];
    }
}

extern "C" void kernel_launch(void* const* d_in, const int* in_sizes, int n_in,
                              void* d_out, int out_size) {
    const float* p0 = (const float*)d_in[0];
    const float* p1 = (const float*)d_in[1];
    const float* feat;
    const float* mem;
    int M;
    if (in_sizes[0] <= in_sizes[1]) { feat = p0; mem = p1; M = in_sizes[1] / D; }
    else                            { feat = p1; mem = p0; M = in_sizes[0] / D; }

    k_mega<<<GRID, TB>>>(feat, mem, (float*)d_out, M);
}

// round 14
// speedup vs baseline: 1.0175x; 1.0175x over previous
#include <cuda_runtime.h>
#include <stdint.h>

#define D 256
#define BQ 1024
#define KTOP 1024
#define MMAX 100000
#define CAND_MAX 4096
#define FEAT_BLOCKS 128
#define HBITS 13
#define HBINS (1 << HBITS)     // 8192 bins
#define GRID 444               // 3 per SM * 148 — co-resident by construction
#define TB 256
#define NBAR 5

typedef unsigned long long ull;

// ---------------- static device scratch ----------------
__device__ ull g_bar;                  // monotonic grid-barrier counter
__device__ float g_pfsum[FEAT_BLOCKS][D];
__device__ float g_fsum[D];
__device__ ull g_keys[MMAX];
__device__ int g_hist[HBINS];          // 32 KB
__device__ int g_Tbin;
__device__ ull g_cand[CAND_MAX];
__device__ int g_ncand;

// ---------------- grid barrier (replay-safe, monotonic epoch base) ----------------
__device__ __forceinline__ void gbar(int k, ull* sbase) {
    __threadfence();                 // release (gpu scope)
    __syncthreads();
    if (threadIdx.x == 0) {
        ull old = atomicAdd(&g_bar, 1ULL);
        if (k == 0) *sbase = old - (old % (ull)(GRID * NBAR));
        ull target = *sbase + (ull)(k + 1) * GRID;
        while (*(volatile ull*)&g_bar < target) __nanosleep(32);
    }
    __syncthreads();
    __threadfence();                 // acquire + L1D invalidate
}

// packed f32x2 FMA (sm_103a FFMA2 — PTX-only)
__device__ __forceinline__ ull fma2(ull a, ull b, ull c) {
    ull d;
    asm("fma.rn.f32x2 %0, %1, %2, %3;" : "=l"(d) : "l"(a), "l"(b), "l"(c));
    return d;
}
__device__ __forceinline__ float unpack_add(ull v) {
    float lo, hi;
    asm("mov.b64 {%0, %1}, %2;" : "=f"(lo), "=f"(hi) : "l"(v));
    return lo + hi;
}

// inclusive suffix-sum over 256 values (one per thread, 8 warps)
__device__ __forceinline__ int suffix256(int v, int t, int lane, int w, int* wsum) {
#pragma unroll
    for (int off = 1; off < 32; off <<= 1) {
        int u = __shfl_down_sync(0xffffffffu, v, off);
        if (lane + off < 32) v += u;
    }
    if (lane == 0) wsum[w] = v;
    __syncthreads();
    if (t < 8) {
        int wv = wsum[t];
#pragma unroll
        for (int off = 1; off < 8; off <<= 1) {
            int u = __shfl_down_sync(0x000000ffu, wv, off);
            if (t + off < 8) wv += u;
        }
        wsum[t] = wv;
    }
    __syncthreads();
    return v + ((w < 7) ? wsum[w + 1] : 0);
}

// load 4 rows (2 ulonglong2 = 4 packed pairs per row per lane), clamped
__device__ __forceinline__ void load4(const float* __restrict__ mem, int rb, int M,
                                      int lane, ulonglong2* A) {
#pragma unroll
    for (int r = 0; r < 4; r++) {
        int row = rb + r;
        if (row >= M) row = M - 1;
        const ulonglong2* m2 = (const ulonglong2*)(mem + (size_t)row * D);
        A[r * 2]     = m2[lane * 2];
        A[r * 2 + 1] = m2[lane * 2 + 1];
    }
}

// ---------------- the mega kernel ----------------
__global__ void __launch_bounds__(TB, 3)
k_mega(const float* __restrict__ feat, const float* __restrict__ mem,
       float* __restrict__ out, int M) {
    __shared__ __align__(16) char s_buf[CAND_MAX * 8];  // 32 KB: shist (P2) / sk (P5)
    __shared__ __align__(16) float sf[D];               // 1 KB: -2*fsum
    __shared__ ull sbase;
    __shared__ int s_ssuf[TB];
    __shared__ int s_wsum[8];

    int t = threadIdx.x, blk = blockIdx.x;
    int warp = t >> 5, lane = t & 31;

    // ---- P0: zero hist + ncand; feature partial sums (blocks 0..127) ----
    {
        int i = blk * TB + t;
        if (i < HBINS) g_hist[i] = 0;
        if (i == 0) g_ncand = 0;
        if (blk < FEAT_BLOCKS) {
            const int RPB = BQ / FEAT_BLOCKS;  // 8
            float s = 0.f;
            int base = blk * RPB * D + t;
#pragma unroll
            for (int r = 0; r < RPB; r++) s += feat[base + r * D];
            g_pfsum[blk][t] = s;
        }
    }
    gbar(0, &sbase);

    // ---- P1: final feature reduction — EXACT R12 numerics (block 0) ----
    if (blk == 0) {
        float s = 0.f;
#pragma unroll 16
        for (int b = 0; b < FEAT_BLOCKS; b++) s += g_pfsum[b][t];
        g_fsum[t] = -2.f * s;
    }
    gbar(1, &sbase);

    // ---- P2: scores — pipelined loads, packed FMA, 6-shfl reduction ----
    {
        int* shist = (int*)s_buf;
        sf[t] = g_fsum[t];
#pragma unroll
        for (int i = t; i < HBINS; i += TB) shist[i] = 0;
        __syncthreads();

        const ulonglong2* f2p = (const ulonglong2*)sf;
        ulonglong2 fA = f2p[lane * 2], fB = f2p[lane * 2 + 1];
        const ull B2 = 0x4480000044800000ULL;  // (1024.f, 1024.f)

        const int STRIDE = GRID * 8 * 4;       // 14208
        int gw = blk * 8 + warp;
        int rb = gw * 4;
        // winner-lane mapping: lanes {0,16,8,24} -> rows +{0,1,2,3}
        int wrow = (lane == 0) ? 0 : (lane == 16) ? 1 : (lane == 8) ? 2
                 : (lane == 24) ? 3 : -1;
        if (rb < M) {
            ulonglong2 A[8];                   // current 4 rows
            load4(mem, rb, M, lane, A);
            while (rb < M) {
                int rb2 = rb + STRIDE;
                ulonglong2 C[8];               // prefetch next 4 rows
                if (rb2 < M) load4(mem, rb2, M, lane, C);

                float acc[4];
#pragma unroll
                for (int r = 0; r < 4; r++) {
                    ull a0 = A[r * 2].x, a1 = A[r * 2].y;
                    ull b0 = A[r * 2 + 1].x, b1 = A[r * 2 + 1].y;
                    ull s2 = fma2(a0, fma2(B2, a0, fA.x), 0ULL);
                    s2 = fma2(a1, fma2(B2, a1, fA.y), s2);
                    s2 = fma2(b0, fma2(B2, b0, fB.x), s2);
                    s2 = fma2(b1, fma2(B2, b1, fB.y), s2);
                    acc[r] = unpack_add(s2);
                }
                // merged reduction: pairing identical to xor-16/8/4/2/1 butterfly
                bool hi16 = (lane & 16) != 0;
                float q0 = __shfl_xor_sync(0xffffffffu, hi16 ? acc[0] : acc[1], 16);
                float z  = (hi16 ? acc[1] : acc[0]) + q0;
                float q1 = __shfl_xor_sync(0xffffffffu, hi16 ? acc[2] : acc[3], 16);
                float w2 = (hi16 ? acc[3] : acc[2]) + q1;
                bool hi8 = (lane & 8) != 0;
                float q2 = __shfl_xor_sync(0xffffffffu, hi8 ? z : w2, 8);
                float v  = (hi8 ? w2 : z) + q2;
                v += __shfl_xor_sync(0xffffffffu, v, 4);
                v += __shfl_xor_sync(0xffffffffu, v, 2);
                v += __shfl_xor_sync(0xffffffffu, v, 1);

                if (wrow >= 0 && rb + wrow < M) {
                    int row = rb + wrow;
                    float score = -v;
                    unsigned u = __float_as_uint(score);
                    u = (u & 0x80000000u) ? ~u : (u | 0x80000000u);
                    g_keys[row] = ((ull)u << 32) | (unsigned)(~row);
                    atomicAdd(&shist[u >> (32 - HBITS)], 1);
                }
#pragma unroll
                for (int j = 0; j < 8; j++) A[j] = C[j];
                rb = rb2;
            }
        }
        __syncthreads();    // all block atomics into shist done
        for (int i = t; i < HBINS; i += TB) {
            int v = shist[i];
            if (v) atomicAdd(&g_hist[i], v);
        }
    }
    gbar(2, &sbase);

    // ---- P3: threshold — single pass, in-register refine (block 0) ----
    if (blk == 0) {
        int h[32];                      // bins [t*32, t*32+32)
        const int4* p4 = (const int4*)(g_hist + t * 32);
        int s = 0;
#pragma unroll
        for (int j = 0; j < 8; j++) {
            int4 v = p4[j];
            h[j * 4] = v.x; h[j * 4 + 1] = v.y; h[j * 4 + 2] = v.z; h[j * 4 + 3] = v.w;
            s += v.x + v.y + v.z + v.w;
        }
        int suf = suffix256(s, t, lane, warp, s_wsum);
        s_ssuf[t] = suf;
        __syncthreads();
        if (suf >= KTOP && (t == TB - 1 || s_ssuf[t + 1] < KTOP)) {
            int cum = (t == TB - 1) ? 0 : s_ssuf[t + 1];
#pragma unroll
            for (int j = 31; j >= 0; j--) {
                cum += h[j];
                if (cum >= KTOP) { g_Tbin = t * 32 + j; break; }
            }
        }
    }
    gbar(3, &sbase);

    // ---- P4: collect candidates ----
    {
        int Tb = g_Tbin;
        for (int i = blk * TB + t; i < M; i += GRID * TB) {
            ull key = g_keys[i];
            if ((int)(key >> (64 - HBITS)) >= Tb) {
                int p = atomicAdd(&g_ncand, 1);
                if (p < CAND_MAX) g_cand[p] = key;
            }
        }
    }
    gbar(4, &sbase);

    // ---- P5 (fused rank+gather): warp per candidate; winner warp copies row ----
    {
        ull* sk = (ull*)s_buf;
        int n = g_ncand;
        if (n > CAND_MAX) n = CAND_MAX;
        for (int j = t; j < n; j += TB) sk[j] = g_cand[j];
        __syncthreads();
        for (int c = blk * 8 + warp; c < n; c += GRID * 8) {
            ull me = sk[c];
            int cnt = 0;
            for (int j = lane; j < n; j += 32) cnt += (sk[j] > me);
#pragma unroll
            for (int o = 16; o > 0; o >>= 1)
                cnt += __shfl_xor_sync(0xffffffffu, cnt, o);   // all lanes get rank
            if (cnt < KTOP) {
                int idx = (int)(~(unsigned)me);                // row index
                const float4* src = (const float4*)(mem + (size_t)idx * D);
                float4* dst = (float4*)(out + (size_t)cnt * D);
#pragma unroll
                for (int j = 0; j < 2; j++)
                    dst[lane + j * 32] = src[lane + j * 32];   // 64 float4 = 1 row
            }
        }
    }
}

extern "C" void kernel_launch(void* const* d_in, const int* in_sizes, int n_in,
                              void* d_out, int out_size) {
    const float* p0 = (const float*)d_in[0];
    const float* p1 = (const float*)d_in[1];
    const float* feat;
    const float* mem;
    int M;
    if (in_sizes[0] <= in_sizes[1]) { feat = p0; mem = p1; M = in_sizes[1] / D; }
    else                            { feat = p1; mem = p0; M = in_sizes[0] / D; }

    k_mega<<<GRID, TB>>>(feat, mem, (float*)d_out, M);
}

// round 15
// speedup vs baseline: 1.2965x; 1.2742x over previous
#include <cuda_runtime.h>
#include <stdint.h>

#define D 256
#define BQ 1024
#define KTOP 1024
#define MMAX 100000
#define CAND_MAX 4096
#define FEAT_BLOCKS 128
#define HBITS 13
#define HBINS (1 << HBITS)     // 8192 bins
#define GRID 444               // 3 per SM * 148 — co-resident by construction
#define TB 256
#define NBAR 6

typedef unsigned long long ull;

// ---------------- static device scratch ----------------
__device__ ull g_bar;                  // monotonic grid-barrier counter
__device__ float g_pfsum[FEAT_BLOCKS][D];
__device__ float g_fsum[D];
__device__ ull g_keys[MMAX];
__device__ int g_hist[HBINS];          // 32 KB
__device__ int g_Tbin;
__device__ ull g_cand[CAND_MAX];
__device__ int g_ncand;
__device__ int g_topidx[KTOP];

// ---------------- grid barrier (replay-safe, monotonic epoch base) ----------------
__device__ __forceinline__ void gbar(int k, ull* sbase) {
    __threadfence();                 // release (gpu scope)
    __syncthreads();
    if (threadIdx.x == 0) {
        ull old = atomicAdd(&g_bar, 1ULL);
        if (k == 0) *sbase = old - (old % (ull)(GRID * NBAR));
        ull target = *sbase + (ull)(k + 1) * GRID;
        while (*(volatile ull*)&g_bar < target) __nanosleep(32);
    }
    __syncthreads();
    __threadfence();                 // acquire + L1D invalidate
}

// packed f32x2 FMA (sm_103a FFMA2 — PTX-only)
__device__ __forceinline__ ull fma2(ull a, ull b, ull c) {
    ull d;
    asm("fma.rn.f32x2 %0, %1, %2, %3;" : "=l"(d) : "l"(a), "l"(b), "l"(c));
    return d;
}
__device__ __forceinline__ float unpack_add(ull v) {
    float lo, hi;
    asm("mov.b64 {%0, %1}, %2;" : "=f"(lo), "=f"(hi) : "l"(v));
    return lo + hi;
}

// inclusive suffix-sum over 256 values (one per thread, 8 warps)
__device__ __forceinline__ int suffix256(int v, int t, int lane, int w, int* wsum) {
#pragma unroll
    for (int off = 1; off < 32; off <<= 1) {
        int u = __shfl_down_sync(0xffffffffu, v, off);
        if (lane + off < 32) v += u;
    }
    if (lane == 0) wsum[w] = v;
    __syncthreads();
    if (t < 8) {
        int wv = wsum[t];
#pragma unroll
        for (int off = 1; off < 8; off <<= 1) {
            int u = __shfl_down_sync(0x000000ffu, wv, off);
            if (t + off < 8) wv += u;
        }
        wsum[t] = wv;
    }
    __syncthreads();
    return v + ((w < 7) ? wsum[w + 1] : 0);
}

// load 4 rows (2 ulonglong2 = 4 packed pairs per row per lane), clamped
__device__ __forceinline__ void load4(const float* __restrict__ mem, int rb, int M,
                                      int lane, ulonglong2* A) {
#pragma unroll
    for (int r = 0; r < 4; r++) {
        int row = rb + r;
        if (row >= M) row = M - 1;
        const ulonglong2* m2 = (const ulonglong2*)(mem + (size_t)row * D);
        A[r * 2]     = m2[lane * 2];
        A[r * 2 + 1] = m2[lane * 2 + 1];
    }
}

// ---------------- the mega kernel ----------------
__global__ void __launch_bounds__(TB, 3)
k_mega(const float* __restrict__ feat, const float* __restrict__ mem,
       float* __restrict__ out, int M) {
    __shared__ __align__(16) char s_buf[CAND_MAX * 8];  // 32 KB: shist (P2) / sk (P5)
    __shared__ __align__(16) float sf[D];               // 1 KB: -2*fsum
    __shared__ ull sbase;
    __shared__ int s_ssuf[TB];
    __shared__ int s_wsum[8];

    int t = threadIdx.x, blk = blockIdx.x;
    int warp = t >> 5, lane = t & 31;

    // ---- P0: zero hist + ncand; feature partial sums (blocks 0..127) ----
    {
        int i = blk * TB + t;
        if (i < HBINS) g_hist[i] = 0;
        if (i == 0) g_ncand = 0;
        if (blk < FEAT_BLOCKS) {
            const int RPB = BQ / FEAT_BLOCKS;  // 8
            float s = 0.f;
            int base = blk * RPB * D + t;
#pragma unroll
            for (int r = 0; r < RPB; r++) s += feat[base + r * D];
            g_pfsum[blk][t] = s;
        }
    }
    gbar(0, &sbase);

    // ---- P1: final feature reduction — EXACT R12 numerics (block 0) ----
    if (blk == 0) {
        float s = 0.f;
#pragma unroll 16
        for (int b = 0; b < FEAT_BLOCKS; b++) s += g_pfsum[b][t];
        g_fsum[t] = -2.f * s;
    }
    gbar(1, &sbase);

    // ---- P2: scores — pipelined loads, packed FMA, 6-shfl reduction ----
    {
        int* shist = (int*)s_buf;
        sf[t] = g_fsum[t];
#pragma unroll
        for (int i = t; i < HBINS; i += TB) shist[i] = 0;
        __syncthreads();

        const ulonglong2* f2p = (const ulonglong2*)sf;
        ulonglong2 fA = f2p[lane * 2], fB = f2p[lane * 2 + 1];
        const ull B2 = 0x4480000044800000ULL;  // (1024.f, 1024.f)

        const int STRIDE = GRID * 8 * 4;       // 14208
        int gw = blk * 8 + warp;
        int rb = gw * 4;
        // winner-lane mapping: lanes {0,16,8,24} -> rows +{0,1,2,3}
        int wrow = (lane == 0) ? 0 : (lane == 16) ? 1 : (lane == 8) ? 2
                 : (lane == 24) ? 3 : -1;
        if (rb < M) {
            ulonglong2 A[8];                   // current 4 rows
            load4(mem, rb, M, lane, A);
            while (rb < M) {
                int rb2 = rb + STRIDE;
                ulonglong2 C[8];               // prefetch next 4 rows
                if (rb2 < M) load4(mem, rb2, M, lane, C);

                float acc[4];
#pragma unroll
                for (int r = 0; r < 4; r++) {
                    ull a0 = A[r * 2].x, a1 = A[r * 2].y;
                    ull b0 = A[r * 2 + 1].x, b1 = A[r * 2 + 1].y;
                    ull s2 = fma2(a0, fma2(B2, a0, fA.x), 0ULL);
                    s2 = fma2(a1, fma2(B2, a1, fA.y), s2);
                    s2 = fma2(b0, fma2(B2, b0, fB.x), s2);
                    s2 = fma2(b1, fma2(B2, b1, fB.y), s2);
                    acc[r] = unpack_add(s2);
                }
                // merged reduction: pairing identical to xor-16/8/4/2/1 butterfly
                bool hi16 = (lane & 16) != 0;
                float q0 = __shfl_xor_sync(0xffffffffu, hi16 ? acc[0] : acc[1], 16);
                float z  = (hi16 ? acc[1] : acc[0]) + q0;
                float q1 = __shfl_xor_sync(0xffffffffu, hi16 ? acc[2] : acc[3], 16);
                float w2 = (hi16 ? acc[3] : acc[2]) + q1;
                bool hi8 = (lane & 8) != 0;
                float q2 = __shfl_xor_sync(0xffffffffu, hi8 ? z : w2, 8);
                float v  = (hi8 ? w2 : z) + q2;
                v += __shfl_xor_sync(0xffffffffu, v, 4);
                v += __shfl_xor_sync(0xffffffffu, v, 2);
                v += __shfl_xor_sync(0xffffffffu, v, 1);

                if (wrow >= 0 && rb + wrow < M) {
                    int row = rb + wrow;
                    float score = -v;
                    unsigned u = __float_as_uint(score);
                    u = (u & 0x80000000u) ? ~u : (u | 0x80000000u);
                    g_keys[row] = ((ull)u << 32) | (unsigned)(~row);
                    atomicAdd(&shist[u >> (32 - HBITS)], 1);
                }
#pragma unroll
                for (int j = 0; j < 8; j++) A[j] = C[j];
                rb = rb2;
            }
        }
        __syncthreads();    // all block atomics into shist done
        for (int i = t; i < HBINS; i += TB) {
            int v = shist[i];
            if (v) atomicAdd(&g_hist[i], v);
        }
    }
    gbar(2, &sbase);

    // ---- P3: threshold — single pass, in-register refine (block 0) ----
    if (blk == 0) {
        int h[32];                      // bins [t*32, t*32+32)
        const int4* p4 = (const int4*)(g_hist + t * 32);
        int s = 0;
#pragma unroll
        for (int j = 0; j < 8; j++) {
            int4 v = p4[j];
            h[j * 4] = v.x; h[j * 4 + 1] = v.y; h[j * 4 + 2] = v.z; h[j * 4 + 3] = v.w;
            s += v.x + v.y + v.z + v.w;
        }
        int suf = suffix256(s, t, lane, warp, s_wsum);
        s_ssuf[t] = suf;
        __syncthreads();
        if (suf >= KTOP && (t == TB - 1 || s_ssuf[t + 1] < KTOP)) {
            int cum = (t == TB - 1) ? 0 : s_ssuf[t + 1];
#pragma unroll
            for (int j = 31; j >= 0; j--) {
                cum += h[j];
                if (cum >= KTOP) { g_Tbin = t * 32 + j; break; }
            }
        }
    }
    gbar(3, &sbase);

    // ---- P4: collect candidates — vectorized 2-key scan ----
    {
        int Tb = g_Tbin;
        const ulonglong2* k2 = (const ulonglong2*)g_keys;
        int half = M >> 1;                      // M even (100000)
        for (int i = blk * TB + t; i < half; i += GRID * TB) {
            ulonglong2 kk = k2[i];
            if ((int)(kk.x >> (64 - HBITS)) >= Tb) {
                int p = atomicAdd(&g_ncand, 1);
                if (p < CAND_MAX) g_cand[p] = kk.x;
            }
            if ((int)(kk.y >> (64 - HBITS)) >= Tb) {
                int p = atomicAdd(&g_ncand, 1);
                if (p < CAND_MAX) g_cand[p] = kk.y;
            }
        }
        // odd tail (not hit for M=100000)
        if ((M & 1) && blk == 0 && t == 0) {
            ull key = g_keys[M - 1];
            if ((int)(key >> (64 - HBITS)) >= Tb) {
                int p = atomicAdd(&g_ncand, 1);
                if (p < CAND_MAX) g_cand[p] = key;
            }
        }
    }
    gbar(4, &sbase);

    // ---- P5: exact rank — warp per candidate (keys unique) ----
    {
        ull* sk = (ull*)s_buf;
        int n = g_ncand;
        if (n > CAND_MAX) n = CAND_MAX;
        for (int j = t; j < n; j += TB) sk[j] = g_cand[j];
        __syncthreads();
        for (int c = blk * 8 + warp; c < n; c += GRID * 8) {
            ull me = sk[c];
            int cnt = 0;
            for (int j = lane; j < n; j += 32) cnt += (sk[j] > me);
#pragma unroll
            for (int o = 16; o > 0; o >>= 1)
                cnt += __shfl_down_sync(0xffffffffu, cnt, o);
            if (lane == 0 && cnt < KTOP) g_topidx[cnt] = (int)(~(unsigned)me);
        }
    }
    gbar(5, &sbase);

    // ---- P6: gather winning rows ----
    for (int rr = blk * 4 + (t >> 6); rr < KTOP; rr += GRID * 4) {
        int idx = g_topidx[rr];
        const float4* src = (const float4*)(mem + (size_t)idx * D);
        float4* dst = (float4*)(out + (size_t)rr * D);
        dst[t & 63] = src[t & 63];
    }
}

extern "C" void kernel_launch(void* const* d_in, const int* in_sizes, int n_in,
                              void* d_out, int out_size) {
    const float* p0 = (const float*)d_in[0];
    const float* p1 = (const float*)d_in[1];
    const float* feat;
    const float* mem;
    int M;
    if (in_sizes[0] <= in_sizes[1]) { feat = p0; mem = p1; M = in_sizes[1] / D; }
    else                            { feat = p1; mem = p0; M = in_sizes[0] / D; }

    k_mega<<<GRID, TB>>>(feat, mem, (float*)d_out, M);
}